// round 1
// baseline (speedup 1.0000x reference)
#include <cuda_runtime.h>
#include <math.h>

#define D_MODEL   256
#define N_HEADS   8
#define HEAD_DIM  32
#define N_LEVELS  3
#define N_POINTS  4
#define N_LP      12
#define B_SZ      16
#define LEN_Q     300
#define N_TOTAL   8400
#define NQ        (B_SZ * LEN_Q)      // 4800
#define P_LD      288                 // 192 offsets + 96 attn logits

// Scratch (allocation-free rule: __device__ globals)
__device__ float g_value  [(size_t)B_SZ * N_TOTAL * D_MODEL]; // 137.6 MB
__device__ float g_params [(size_t)NQ * P_LD];
__device__ float g_sampled[(size_t)NQ * D_MODEL];

// ---------------------------------------------------------------------------
// Tiled fp32 GEMM with bias: C[M,ldc] = A[M,K] @ W[K,N] + bias[N]
// BM=128, BN=64, BK=16, per-thread 8x4, 256 threads.
// ---------------------------------------------------------------------------
__global__ __launch_bounds__(256, 2)
void gemm_bias_kernel(const float* __restrict__ A,
                      const float* __restrict__ W,
                      const float* __restrict__ bias,
                      float* __restrict__ C,
                      int M, int N, int K, int ldc)
{
    __shared__ float As[16][128];   // As[k][m]
    __shared__ float Bs[16][64];    // Bs[k][n]

    const int bm  = blockIdx.y * 128;
    const int bn  = blockIdx.x * 64;
    const int tid = threadIdx.x;
    const int tx  = tid & 15;       // n dir (x4)
    const int ty  = tid >> 4;       // m dir (x8)

    float acc[8][4];
#pragma unroll
    for (int i = 0; i < 8; ++i)
#pragma unroll
        for (int j = 0; j < 4; ++j) acc[i][j] = 0.f;

    const int a_row  = tid >> 2;          // 0..63
    const int a_col  = (tid & 3) << 2;    // 0,4,8,12
    const int b_row  = tid >> 4;          // 0..15
    const int b_col  = (tid & 15) << 2;   // 0..60

    for (int k0 = 0; k0 < K; k0 += 16) {
        // ---- load A tile (128x16), transpose into As[k][m]
#pragma unroll
        for (int i = 0; i < 2; ++i) {
            int m  = a_row + i * 64;
            int gm = bm + m;
            float4 v = make_float4(0.f, 0.f, 0.f, 0.f);
            if (gm < M)
                v = *(const float4*)(A + (size_t)gm * K + k0 + a_col);
            As[a_col + 0][m] = v.x;
            As[a_col + 1][m] = v.y;
            As[a_col + 2][m] = v.z;
            As[a_col + 3][m] = v.w;
        }
        // ---- load B tile (16x64)
        {
            int gn = bn + b_col;
            int gk = k0 + b_row;
            float4 v = make_float4(0.f, 0.f, 0.f, 0.f);
            if (gn + 3 < N) {
                v = *(const float4*)(W + (size_t)gk * N + gn);
            } else {
                float* pv = (float*)&v;
#pragma unroll
                for (int j = 0; j < 4; ++j)
                    if (gn + j < N) pv[j] = W[(size_t)gk * N + gn + j];
            }
            *(float4*)&Bs[b_row][b_col] = v;
        }
        __syncthreads();

#pragma unroll
        for (int k = 0; k < 16; ++k) {
            float4 a0 = *(const float4*)&As[k][ty * 8];
            float4 a1 = *(const float4*)&As[k][ty * 8 + 4];
            float4 b0 = *(const float4*)&Bs[k][tx * 4];
            float ra[8] = {a0.x, a0.y, a0.z, a0.w, a1.x, a1.y, a1.z, a1.w};
            float rb[4] = {b0.x, b0.y, b0.z, b0.w};
#pragma unroll
            for (int i = 0; i < 8; ++i)
#pragma unroll
                for (int j = 0; j < 4; ++j)
                    acc[i][j] += ra[i] * rb[j];
        }
        __syncthreads();
    }

    // ---- epilogue with bias
    float bv[4];
#pragma unroll
    for (int j = 0; j < 4; ++j) {
        int gn = bn + tx * 4 + j;
        bv[j] = (gn < N) ? bias[gn] : 0.f;
    }
#pragma unroll
    for (int i = 0; i < 8; ++i) {
        int gm = bm + ty * 8 + i;
        if (gm >= M) continue;
#pragma unroll
        for (int j = 0; j < 4; ++j) {
            int gn = bn + tx * 4 + j;
            if (gn < N) C[(size_t)gm * ldc + gn] = acc[i][j] + bv[j];
        }
    }
}

// ---------------------------------------------------------------------------
// Deformable sampling + softmax.
// grid = NQ blocks, 256 threads: warp = head, lane = head-dim channel.
// g_value layout: [b][n][h*32+hd] => per-(head,location) gather of 32 floats
// is one coalesced 128B transaction per warp.
// ---------------------------------------------------------------------------
__global__ __launch_bounds__(256)
void sample_kernel(const float* __restrict__ ref,   // (B, LEN_Q, 3, 2)
                   float* __restrict__ out)          // g_sampled (NQ, 256)
{
    const int row  = blockIdx.x;          // b*LEN_Q + q
    const int b    = row / LEN_Q;
    const int h    = threadIdx.x >> 5;
    const int lane = threadIdx.x & 31;

    const int   lvl_start[3] = {0, 6400, 8000};
    const int   lvl_W[3]     = {80, 40, 20};
    const float lvl_inv[3]   = {1.f / 80.f, 1.f / 40.f, 1.f / 20.f};

    const float* prm  = g_params + (size_t)row * P_LD;
    const float* offp = prm + h * (N_LP * 2);
    const float* attp = prm + 192 + h * N_LP;

    // softmax over 12 attn logits (lanes 0..11 hold them)
    float lgt = (lane < N_LP) ? attp[lane] : -3.0e38f;
    float mx = lgt;
#pragma unroll
    for (int s = 16; s; s >>= 1) mx = fmaxf(mx, __shfl_xor_sync(0xffffffffu, mx, s));
    float e = (lane < N_LP) ? expf(lgt - mx) : 0.f;
    float sum = e;
#pragma unroll
    for (int s = 16; s; s >>= 1) sum += __shfl_xor_sync(0xffffffffu, sum, s);
    float wnorm = e / sum;

    const float* rp    = ref + (size_t)row * N_LEVELS * 2;
    const float* vbase = g_value + (size_t)b * N_TOTAL * D_MODEL + h * HEAD_DIM + lane;

    float acc = 0.f;
#pragma unroll
    for (int j = 0; j < N_LP; ++j) {
        const int l  = j >> 2;
        const int Wl = lvl_W[l];
        const int st = lvl_start[l];

        float aw = __shfl_sync(0xffffffffu, wnorm, j);

        float ox = offp[2 * j + 0];
        float oy = offp[2 * j + 1];
        float lx = rp[2 * l + 0] + ox * lvl_inv[l];
        float ly = rp[2 * l + 1] + oy * lvl_inv[l];

        float ix = lx * (float)Wl - 0.5f;   // H == W for all levels
        float iy = ly * (float)Wl - 0.5f;
        float fix = floorf(ix), fiy = floorf(iy);
        int   x0 = (int)fix,   y0 = (int)fiy;
        float fx = ix - fix,   fy = iy - fiy;
        int   x1 = x0 + 1,     y1 = y0 + 1;

        bool vx0 = (x0 >= 0) & (x0 < Wl);
        bool vx1 = (x1 >= 0) & (x1 < Wl);
        bool vy0 = (y0 >= 0) & (y0 < Wl);
        bool vy1 = (y1 >= 0) & (y1 < Wl);

        float v00 = (vy0 & vx0) ? vbase[(size_t)(st + y0 * Wl + x0) * D_MODEL] : 0.f;
        float v01 = (vy0 & vx1) ? vbase[(size_t)(st + y0 * Wl + x1) * D_MODEL] : 0.f;
        float v10 = (vy1 & vx0) ? vbase[(size_t)(st + y1 * Wl + x0) * D_MODEL] : 0.f;
        float v11 = (vy1 & vx1) ? vbase[(size_t)(st + y1 * Wl + x1) * D_MODEL] : 0.f;

        float bil = (1.f - fx) * (1.f - fy) * v00 + fx * (1.f - fy) * v01
                  + (1.f - fx) * fy         * v10 + fx * fy         * v11;
        acc += aw * bil;
    }

    out[(size_t)row * D_MODEL + h * HEAD_DIM + lane] = acc;
}

// ---------------------------------------------------------------------------
extern "C" void kernel_launch(void* const* d_in, const int* in_sizes, int n_in,
                              void* d_out, int out_size)
{
    const float* query  = (const float*)d_in[0];   // (16,300,256)
    const float* refpts = (const float*)d_in[1];   // (16,300,3,2)
    const float* inputf = (const float*)d_in[2];   // (16,8400,256)
    const float* W_off  = (const float*)d_in[3];   // (256,192)
    const float* b_off  = (const float*)d_in[4];
    const float* W_attn = (const float*)d_in[5];   // (256,96)
    const float* b_attn = (const float*)d_in[6];
    const float* W_val  = (const float*)d_in[7];   // (256,256)
    const float* b_val  = (const float*)d_in[8];
    const float* W_out  = (const float*)d_in[9];   // (256,256)
    const float* b_out  = (const float*)d_in[10];
    float* outp = (float*)d_out;

    float* value;   cudaGetSymbolAddress((void**)&value,   g_value);
    float* params;  cudaGetSymbolAddress((void**)&params,  g_params);
    float* sampled; cudaGetSymbolAddress((void**)&sampled, g_sampled);

    // 1. value projection: (134400,256) @ (256,256) + b_val
    {
        dim3 grid(256 / 64, (B_SZ * N_TOTAL + 127) / 128);
        gemm_bias_kernel<<<grid, 256>>>(inputf, W_val, b_val, value,
                                        B_SZ * N_TOTAL, D_MODEL, D_MODEL, D_MODEL);
    }
    // 2a. offsets: (4800,256) @ (256,192) -> params cols [0,192)
    {
        dim3 grid((192 + 63) / 64, (NQ + 127) / 128);
        gemm_bias_kernel<<<grid, 256>>>(query, W_off, b_off, params,
                                        NQ, 192, D_MODEL, P_LD);
    }
    // 2b. attn logits: (4800,256) @ (256,96) -> params cols [192,288)
    {
        dim3 grid((96 + 63) / 64, (NQ + 127) / 128);
        gemm_bias_kernel<<<grid, 256>>>(query, W_attn, b_attn, params + 192,
                                        NQ, 96, D_MODEL, P_LD);
    }
    // 3. softmax + deformable bilinear sampling
    sample_kernel<<<NQ, 256>>>(refpts, sampled);

    // 4. output projection: (4800,256) @ (256,256) + b_out -> d_out
    {
        dim3 grid(256 / 64, (NQ + 127) / 128);
        gemm_bias_kernel<<<grid, 256>>>(sampled, W_out, b_out, outp,
                                        NQ, D_MODEL, D_MODEL, D_MODEL);
    }
    (void)in_sizes; (void)n_in; (void)out_size;
}

// round 2
// speedup vs baseline: 2.0101x; 2.0101x over previous
#include <cuda_runtime.h>
#include <math.h>

#define D_MODEL   256
#define N_HEADS   8
#define HEAD_DIM  32
#define N_LEVELS  3
#define N_POINTS  4
#define N_LP      12
#define B_SZ      16
#define LEN_Q     300
#define N_TOTAL   8400
#define NQ        (B_SZ * LEN_Q)      // 4800
#define P_LD      288                 // 192 offsets + 96 attn logits
#define M1        (B_SZ * N_TOTAL)    // 134400

// Scratch (allocation-free rule: __device__ globals)
__device__ float g_value  [(size_t)M1 * D_MODEL]; // 137.6 MB
__device__ float g_params [(size_t)NQ * P_LD];
__device__ float g_sampled[(size_t)NQ * D_MODEL];

// ---------------------------------------------------------------------------
// TF32 tensor-core GEMM: C[M,256] = A[M,256] @ W[256,256] + bias
// BM=128, BN=128, BK=16, 8 warps (2x4), warp tile 64x32, mma.m16n8k8.tf32.
// Requires M % 128 == 0, N == 256, K == 256.
// ---------------------------------------------------------------------------
__device__ __forceinline__ float f2tf32(float x) {
    unsigned r;
    asm("cvt.rna.tf32.f32 %0, %1;" : "=r"(r) : "f"(x));
    return __uint_as_float(r);
}

__device__ __forceinline__ void mma_tf32(float c[4], float a0, float a1, float a2, float a3,
                                         float b0, float b1) {
    asm volatile(
        "mma.sync.aligned.m16n8k8.row.col.f32.tf32.tf32.f32 "
        "{%0,%1,%2,%3}, {%4,%5,%6,%7}, {%8,%9}, {%0,%1,%2,%3};"
        : "+f"(c[0]), "+f"(c[1]), "+f"(c[2]), "+f"(c[3])
        : "r"(__float_as_uint(a0)), "r"(__float_as_uint(a1)),
          "r"(__float_as_uint(a2)), "r"(__float_as_uint(a3)),
          "r"(__float_as_uint(b0)), "r"(__float_as_uint(b1)));
}

#define AS_STRIDE 20    // (20*r + c) % 32 distinct over r:0..7, c:0..3 -> conflict-free
#define BS_STRIDE 136   // (136*k + n) % 32 = (8k+n)%32 distinct -> conflict-free

__global__ __launch_bounds__(256, 2)
void gemm_tf32_kernel(const float* __restrict__ A,
                      const float* __restrict__ W,
                      const float* __restrict__ bias,
                      float* __restrict__ C,
                      int M)
{
    __shared__ float As[2][128][AS_STRIDE];  // [stage][m][k]
    __shared__ float Bs[2][16][BS_STRIDE];   // [stage][k][n]

    const int K = 256;
    const int bm = blockIdx.y * 128;
    const int bn = blockIdx.x * 128;
    const int tid  = threadIdx.x;
    const int warp = tid >> 5;
    const int lane = tid & 31;
    const int g  = lane >> 2;    // 0..7
    const int t4 = lane & 3;     // 0..3
    const int mo = (warp >> 2) * 64;   // 0 or 64
    const int no = (warp & 3) * 32;    // 0,32,64,96

    float acc[4][4][4];
#pragma unroll
    for (int i = 0; i < 4; ++i)
#pragma unroll
        for (int j = 0; j < 4; ++j)
#pragma unroll
            for (int r = 0; r < 4; ++r) acc[i][j][r] = 0.f;

    // load indices: A tile 128x16 = 512 float4; B tile 16x128 = 512 float4
    const int a_r0 = tid >> 1;            // with idx = tid + i*256
    // (computed per-iteration below)

    float4 pa[2], pb[2];

    // ---- prologue: load chunk 0
#pragma unroll
    for (int i = 0; i < 2; ++i) {
        int idx = tid + i * 256;
        int ar = idx >> 2, ac = (idx & 3) << 2;
        pa[i] = *(const float4*)(A + (size_t)(bm + ar) * K + ac);
        int br = idx >> 5, bc = (idx & 31) << 2;
        pb[i] = *(const float4*)(W + (size_t)br * 256 + bn + bc);
    }
#pragma unroll
    for (int i = 0; i < 2; ++i) {
        int idx = tid + i * 256;
        int ar = idx >> 2, ac = (idx & 3) << 2;
        As[0][ar][ac + 0] = f2tf32(pa[i].x);
        As[0][ar][ac + 1] = f2tf32(pa[i].y);
        As[0][ar][ac + 2] = f2tf32(pa[i].z);
        As[0][ar][ac + 3] = f2tf32(pa[i].w);
        int br = idx >> 5, bc = (idx & 31) << 2;
        Bs[0][br][bc + 0] = f2tf32(pb[i].x);
        Bs[0][br][bc + 1] = f2tf32(pb[i].y);
        Bs[0][br][bc + 2] = f2tf32(pb[i].z);
        Bs[0][br][bc + 3] = f2tf32(pb[i].w);
    }
    __syncthreads();

    const int NCHUNK = 16;  // K / 16
    for (int c = 0; c < NCHUNK; ++c) {
        const int cur = c & 1, nxt = cur ^ 1;
        const int k0n = (c + 1) * 16;

        // prefetch next chunk into regs
        if (c < NCHUNK - 1) {
#pragma unroll
            for (int i = 0; i < 2; ++i) {
                int idx = tid + i * 256;
                int ar = idx >> 2, ac = (idx & 3) << 2;
                pa[i] = *(const float4*)(A + (size_t)(bm + ar) * K + k0n + ac);
                int br = idx >> 5, bc = (idx & 31) << 2;
                pb[i] = *(const float4*)(W + (size_t)(k0n + br) * 256 + bn + bc);
            }
        }

        // compute current stage: two k8 steps
#pragma unroll
        for (int kk = 0; kk < 16; kk += 8) {
            float af[4][4];
#pragma unroll
            for (int i = 0; i < 4; ++i) {
                af[i][0] = As[cur][mo + 16 * i + g    ][kk + t4];
                af[i][1] = As[cur][mo + 16 * i + g + 8][kk + t4];
                af[i][2] = As[cur][mo + 16 * i + g    ][kk + t4 + 4];
                af[i][3] = As[cur][mo + 16 * i + g + 8][kk + t4 + 4];
            }
            float bf[4][2];
#pragma unroll
            for (int j = 0; j < 4; ++j) {
                bf[j][0] = Bs[cur][kk + t4    ][no + 8 * j + g];
                bf[j][1] = Bs[cur][kk + t4 + 4][no + 8 * j + g];
            }
#pragma unroll
            for (int i = 0; i < 4; ++i)
#pragma unroll
                for (int j = 0; j < 4; ++j)
                    mma_tf32(acc[i][j], af[i][0], af[i][1], af[i][2], af[i][3],
                             bf[j][0], bf[j][1]);
        }

        // store prefetched chunk into next stage
        if (c < NCHUNK - 1) {
#pragma unroll
            for (int i = 0; i < 2; ++i) {
                int idx = tid + i * 256;
                int ar = idx >> 2, ac = (idx & 3) << 2;
                As[nxt][ar][ac + 0] = f2tf32(pa[i].x);
                As[nxt][ar][ac + 1] = f2tf32(pa[i].y);
                As[nxt][ar][ac + 2] = f2tf32(pa[i].z);
                As[nxt][ar][ac + 3] = f2tf32(pa[i].w);
                int br = idx >> 5, bc = (idx & 31) << 2;
                Bs[nxt][br][bc + 0] = f2tf32(pb[i].x);
                Bs[nxt][br][bc + 1] = f2tf32(pb[i].y);
                Bs[nxt][br][bc + 2] = f2tf32(pb[i].z);
                Bs[nxt][br][bc + 3] = f2tf32(pb[i].w);
            }
        }
        __syncthreads();
    }

    // ---- epilogue with bias (c0,c1 adjacent cols -> float2 stores)
#pragma unroll
    for (int j = 0; j < 4; ++j) {
        int gn = bn + no + 8 * j + 2 * t4;
        float b0 = bias[gn], b1 = bias[gn + 1];
#pragma unroll
        for (int i = 0; i < 4; ++i) {
            int gm = bm + mo + 16 * i + g;
            float2 v0 = make_float2(acc[i][j][0] + b0, acc[i][j][1] + b1);
            *(float2*)(C + (size_t)gm * 256 + gn) = v0;
            float2 v1 = make_float2(acc[i][j][2] + b0, acc[i][j][3] + b1);
            *(float2*)(C + (size_t)(gm + 8) * 256 + gn) = v1;
        }
    }
}

// ---------------------------------------------------------------------------
// Exact fp32 tiled GEMM with bias (small matrices): C = A@W + bias
// BM=128, BN=64, BK=16, per-thread 8x4, 256 threads.
// ---------------------------------------------------------------------------
__global__ __launch_bounds__(256, 2)
void gemm_bias_kernel(const float* __restrict__ A,
                      const float* __restrict__ W,
                      const float* __restrict__ bias,
                      float* __restrict__ C,
                      int M, int N, int K, int ldc)
{
    __shared__ float As[16][128];
    __shared__ float Bs[16][64];

    const int bm  = blockIdx.y * 128;
    const int bn  = blockIdx.x * 64;
    const int tid = threadIdx.x;
    const int tx  = tid & 15;
    const int ty  = tid >> 4;

    float acc[8][4];
#pragma unroll
    for (int i = 0; i < 8; ++i)
#pragma unroll
        for (int j = 0; j < 4; ++j) acc[i][j] = 0.f;

    const int a_row = tid >> 2;
    const int a_col = (tid & 3) << 2;
    const int b_row = tid >> 4;
    const int b_col = (tid & 15) << 2;

    for (int k0 = 0; k0 < K; k0 += 16) {
#pragma unroll
        for (int i = 0; i < 2; ++i) {
            int m  = a_row + i * 64;
            int gm = bm + m;
            float4 v = make_float4(0.f, 0.f, 0.f, 0.f);
            if (gm < M)
                v = *(const float4*)(A + (size_t)gm * K + k0 + a_col);
            As[a_col + 0][m] = v.x;
            As[a_col + 1][m] = v.y;
            As[a_col + 2][m] = v.z;
            As[a_col + 3][m] = v.w;
        }
        {
            int gn = bn + b_col;
            int gk = k0 + b_row;
            float4 v = make_float4(0.f, 0.f, 0.f, 0.f);
            if (gn + 3 < N) {
                v = *(const float4*)(W + (size_t)gk * N + gn);
            } else {
                float* pv = (float*)&v;
#pragma unroll
                for (int j = 0; j < 4; ++j)
                    if (gn + j < N) pv[j] = W[(size_t)gk * N + gn + j];
            }
            *(float4*)&Bs[b_row][b_col] = v;
        }
        __syncthreads();

#pragma unroll
        for (int k = 0; k < 16; ++k) {
            float4 a0 = *(const float4*)&As[k][ty * 8];
            float4 a1 = *(const float4*)&As[k][ty * 8 + 4];
            float4 b0 = *(const float4*)&Bs[k][tx * 4];
            float ra[8] = {a0.x, a0.y, a0.z, a0.w, a1.x, a1.y, a1.z, a1.w};
            float rb[4] = {b0.x, b0.y, b0.z, b0.w};
#pragma unroll
            for (int i = 0; i < 8; ++i)
#pragma unroll
                for (int j = 0; j < 4; ++j)
                    acc[i][j] += ra[i] * rb[j];
        }
        __syncthreads();
    }

    float bv[4];
#pragma unroll
    for (int j = 0; j < 4; ++j) {
        int gn = bn + tx * 4 + j;
        bv[j] = (gn < N) ? bias[gn] : 0.f;
    }
#pragma unroll
    for (int i = 0; i < 8; ++i) {
        int gm = bm + ty * 8 + i;
        if (gm >= M) continue;
#pragma unroll
        for (int j = 0; j < 4; ++j) {
            int gn = bn + tx * 4 + j;
            if (gn < N) C[(size_t)gm * ldc + gn] = acc[i][j] + bv[j];
        }
    }
}

// ---------------------------------------------------------------------------
// Deformable sampling + softmax. warp = head, lane = head-dim channel.
// ---------------------------------------------------------------------------
__global__ __launch_bounds__(256)
void sample_kernel(const float* __restrict__ ref,
                   float* __restrict__ out)
{
    const int row  = blockIdx.x;
    const int b    = row / LEN_Q;
    const int h    = threadIdx.x >> 5;
    const int lane = threadIdx.x & 31;

    const int   lvl_start[3] = {0, 6400, 8000};
    const int   lvl_W[3]     = {80, 40, 20};
    const float lvl_inv[3]   = {1.f / 80.f, 1.f / 40.f, 1.f / 20.f};

    const float* prm  = g_params + (size_t)row * P_LD;
    const float* offp = prm + h * (N_LP * 2);
    const float* attp = prm + 192 + h * N_LP;

    float lgt = (lane < N_LP) ? attp[lane] : -3.0e38f;
    float mx = lgt;
#pragma unroll
    for (int s = 16; s; s >>= 1) mx = fmaxf(mx, __shfl_xor_sync(0xffffffffu, mx, s));
    float e = (lane < N_LP) ? expf(lgt - mx) : 0.f;
    float sum = e;
#pragma unroll
    for (int s = 16; s; s >>= 1) sum += __shfl_xor_sync(0xffffffffu, sum, s);
    float wnorm = e / sum;

    const float* rp    = ref + (size_t)row * N_LEVELS * 2;
    const float* vbase = g_value + (size_t)b * N_TOTAL * D_MODEL + h * HEAD_DIM + lane;

    float acc = 0.f;
#pragma unroll
    for (int j = 0; j < N_LP; ++j) {
        const int l  = j >> 2;
        const int Wl = lvl_W[l];
        const int st = lvl_start[l];

        float aw = __shfl_sync(0xffffffffu, wnorm, j);

        float ox = offp[2 * j + 0];
        float oy = offp[2 * j + 1];
        float lx = rp[2 * l + 0] + ox * lvl_inv[l];
        float ly = rp[2 * l + 1] + oy * lvl_inv[l];

        float ix = lx * (float)Wl - 0.5f;
        float iy = ly * (float)Wl - 0.5f;
        float fix = floorf(ix), fiy = floorf(iy);
        int   x0 = (int)fix,   y0 = (int)fiy;
        float fx = ix - fix,   fy = iy - fiy;
        int   x1 = x0 + 1,     y1 = y0 + 1;

        bool vx0 = (x0 >= 0) & (x0 < Wl);
        bool vx1 = (x1 >= 0) & (x1 < Wl);
        bool vy0 = (y0 >= 0) & (y0 < Wl);
        bool vy1 = (y1 >= 0) & (y1 < Wl);

        float v00 = (vy0 & vx0) ? vbase[(size_t)(st + y0 * Wl + x0) * D_MODEL] : 0.f;
        float v01 = (vy0 & vx1) ? vbase[(size_t)(st + y0 * Wl + x1) * D_MODEL] : 0.f;
        float v10 = (vy1 & vx0) ? vbase[(size_t)(st + y1 * Wl + x0) * D_MODEL] : 0.f;
        float v11 = (vy1 & vx1) ? vbase[(size_t)(st + y1 * Wl + x1) * D_MODEL] : 0.f;

        float bil = (1.f - fx) * (1.f - fy) * v00 + fx * (1.f - fy) * v01
                  + (1.f - fx) * fy         * v10 + fx * fy         * v11;
        acc += aw * bil;
    }

    out[(size_t)row * D_MODEL + h * HEAD_DIM + lane] = acc;
}

// ---------------------------------------------------------------------------
extern "C" void kernel_launch(void* const* d_in, const int* in_sizes, int n_in,
                              void* d_out, int out_size)
{
    const float* query  = (const float*)d_in[0];
    const float* refpts = (const float*)d_in[1];
    const float* inputf = (const float*)d_in[2];
    const float* W_off  = (const float*)d_in[3];
    const float* b_off  = (const float*)d_in[4];
    const float* W_attn = (const float*)d_in[5];
    const float* b_attn = (const float*)d_in[6];
    const float* W_val  = (const float*)d_in[7];
    const float* b_val  = (const float*)d_in[8];
    const float* W_out  = (const float*)d_in[9];
    const float* b_out  = (const float*)d_in[10];
    float* outp = (float*)d_out;

    float* value;   cudaGetSymbolAddress((void**)&value,   g_value);
    float* params;  cudaGetSymbolAddress((void**)&params,  g_params);
    float* sampled; cudaGetSymbolAddress((void**)&sampled, g_sampled);

    // 1. value projection (tensor cores, tf32): (134400,256)@(256,256)+b
    {
        dim3 grid(2, M1 / 128);   // N/128, M/128
        gemm_tf32_kernel<<<grid, 256>>>(inputf, W_val, b_val, value, M1);
    }
    // 2a. offsets (exact fp32)
    {
        dim3 grid((192 + 63) / 64, (NQ + 127) / 128);
        gemm_bias_kernel<<<grid, 256>>>(query, W_off, b_off, params,
                                        NQ, 192, D_MODEL, P_LD);
    }
    // 2b. attn logits (exact fp32)
    {
        dim3 grid((96 + 63) / 64, (NQ + 127) / 128);
        gemm_bias_kernel<<<grid, 256>>>(query, W_attn, b_attn, params + 192,
                                        NQ, 96, D_MODEL, P_LD);
    }
    // 3. softmax + deformable bilinear sampling
    sample_kernel<<<NQ, 256>>>(refpts, sampled);

    // 4. output projection (exact fp32)
    {
        dim3 grid(256 / 64, (NQ + 127) / 128);
        gemm_bias_kernel<<<grid, 256>>>(sampled, W_out, b_out, outp,
                                        NQ, D_MODEL, D_MODEL, D_MODEL);
    }
    (void)in_sizes; (void)n_in; (void)out_size;
}

// round 4
// speedup vs baseline: 2.0459x; 1.0178x over previous
#include <cuda_runtime.h>
#include <math.h>
#include <stdint.h>

#define D_MODEL   256
#define N_HEADS   8
#define HEAD_DIM  32
#define N_LEVELS  3
#define N_POINTS  4
#define N_LP      12
#define B_SZ      16
#define LEN_Q     300
#define N_TOTAL   8400
#define NQ        (B_SZ * LEN_Q)      // 4800
#define P_LD      288
#define M1        (B_SZ * N_TOTAL)    // 134400

// Scratch (__device__ globals per allocation-free rule)
__device__ float g_value  [(size_t)M1 * D_MODEL];
__device__ float g_params [(size_t)NQ * P_LD];
__device__ float g_sampled[(size_t)NQ * D_MODEL];
__device__ float g_Bfrag  [256 * 256];   // W_val in mma B-fragment order, tf32-rounded

// ---------------------------------------------------------------------------
__device__ __forceinline__ float f2tf32(float x) {
    unsigned r;
    asm("cvt.rna.tf32.f32 %0, %1;" : "=r"(r) : "f"(x));
    return __uint_as_float(r);
}
__device__ __forceinline__ uint32_t smem_u32(const void* p) {
    uint32_t a;
    asm("{ .reg .u64 t; cvta.to.shared.u64 t, %1; cvt.u32.u64 %0, t; }"
        : "=r"(a) : "l"(p));
    return a;
}
__device__ __forceinline__ void cp_async16(uint32_t dst, const void* src) {
    asm volatile("cp.async.cg.shared.global [%0], [%1], 16;"
                 :: "r"(dst), "l"(src) : "memory");
}
__device__ __forceinline__ void cp_commit() {
    asm volatile("cp.async.commit_group;" ::: "memory");
}
__device__ __forceinline__ void cp_wait0() {
    asm volatile("cp.async.wait_group 0;" ::: "memory");
}
__device__ __forceinline__ void mma_tf32(float c[4], float a0, float a1, float a2, float a3,
                                         float b0, float b1) {
    asm volatile(
        "mma.sync.aligned.m16n8k8.row.col.f32.tf32.tf32.f32 "
        "{%0,%1,%2,%3}, {%4,%5,%6,%7}, {%8,%9}, {%0,%1,%2,%3};"
        : "+f"(c[0]), "+f"(c[1]), "+f"(c[2]), "+f"(c[3])
        : "r"(__float_as_uint(a0)), "r"(__float_as_uint(a1)),
          "r"(__float_as_uint(a2)), "r"(__float_as_uint(a3)),
          "r"(__float_as_uint(b0)), "r"(__float_as_uint(b1)));
}

// ---------------------------------------------------------------------------
// Pre-transform W_val[k][n] -> g_Bfrag in B-fragment order (tf32 rounded).
// For k-chunk kc (32), kk8 = (k%32)/8, t4 = k%4, half = (k%8)>=4:
//   g_Bfrag[((kc*4+kk8)*256 + n)*8 + t4*2 + half] = rna(W[k][n])
// Each 32-KB contiguous block == one smem B stage image.
// ---------------------------------------------------------------------------
__global__ void prep_w_kernel(const float* __restrict__ W) {
    int id = blockIdx.x * 256 + threadIdx.x;   // 0..65535
    int k = id >> 8, n = id & 255;
    int kc = k >> 5, kk8 = (k >> 3) & 3, t4v = k & 3, half = (k >> 2) & 1;
    size_t pos = (size_t)(((kc * 4 + kk8) * 256 + n) * 8 + t4v * 2 + half);
    g_Bfrag[pos] = f2tf32(W[(size_t)k * 256 + n]);
}

// ---------------------------------------------------------------------------
// GEMM1: C[M1,256] = A[M1,256] @ W + bias   (mma.sync tf32)
// CTA 128x256, BK=32, double-buffered. 8 warps, warp tile 64x64.
// smem layout (floats):
//   sA[st]: [kk8(4)][mtile(8)][lane(32)][slot(4)]  = 4096 fl per stage
//   sB[st]: raw copy of g_Bfrag chunk              = 8192 fl per stage
// ---------------------------------------------------------------------------
#define GEMM1_DYN (96 * 1024)

__global__ __launch_bounds__(256, 1)
void gemm1_mma_kernel(const float* __restrict__ A,
                      const float* __restrict__ bias,
                      float* __restrict__ C)
{
    extern __shared__ float smem[];
    float* sA[2] = { smem,        smem + 4096 };
    float* sB[2] = { smem + 8192, smem + 16384 };

    const int tid  = threadIdx.x;
    const int warp = tid >> 5;
    const int lane = tid & 31;
    const int g    = lane >> 2;
    const int t4   = lane & 3;
    const int mo   = (warp >> 2) * 4;    // m16-tile base: 0 or 4
    const int no   = (warp & 3) * 64;    // n base
    const int bm   = blockIdx.x * 128;

    float acc[4][8][4];
#pragma unroll
    for (int i = 0; i < 4; ++i)
#pragma unroll
        for (int j = 0; j < 8; ++j)
#pragma unroll
            for (int r = 0; r < 4; ++r) acc[i][j][r] = 0.f;

    float4 ra[4];

    // ---- helpers inlined: A ldg for chunk c; A sts to stage s
#define LDA(c)                                                                 \
    do {                                                                       \
        _Pragma("unroll")                                                      \
        for (int i = 0; i < 4; ++i) {                                          \
            int idx = tid + i * 256;                                           \
            int ar = idx >> 3, ac = idx & 7;                                   \
            ra[i] = *(const float4*)(A + (size_t)(bm + ar) * 256 + (c) * 32 + ac * 4); \
        }                                                                      \
    } while (0)

#define STA(s)                                                                 \
    do {                                                                       \
        _Pragma("unroll")                                                      \
        for (int i = 0; i < 4; ++i) {                                          \
            int idx = tid + i * 256;                                           \
            int ar = idx >> 3, ac = idx & 7;                                   \
            int r = ar & 15, mt = ar >> 4;                                     \
            int gl = r & 7, hi = r >> 3;                                       \
            float v[4] = { ra[i].x, ra[i].y, ra[i].z, ra[i].w };               \
            _Pragma("unroll")                                                  \
            for (int e = 0; e < 4; ++e) {                                      \
                int kl = ac * 4 + e;                                           \
                int kk8 = kl >> 3, t4v = kl & 3, half = (kl >> 2) & 1;         \
                sA[s][((kk8 * 8 + mt) * 32 + gl * 4 + t4v) * 4 + half * 2 + hi] = f2tf32(v[e]); \
            }                                                                  \
        }                                                                      \
    } while (0)

#define LDB_ASYNC(c, s)                                                        \
    do {                                                                       \
        uint32_t base = smem_u32(sB[s]);                                       \
        const float* src = g_Bfrag + (size_t)(c) * 8192;                       \
        _Pragma("unroll")                                                      \
        for (int i = 0; i < 8; ++i) {                                          \
            int off = (tid + i * 256) * 4;                                     \
            cp_async16(base + off * 4, src + off);                             \
        }                                                                      \
        cp_commit();                                                           \
    } while (0)

    // ---- prologue: chunk 0
    LDA(0);
    LDB_ASYNC(0, 0);
    STA(0);
    cp_wait0();
    __syncthreads();

#pragma unroll 1
    for (int c = 0; c < 8; ++c) {
        const int st = c & 1;
        const bool more = (c < 7);
        if (more) { LDA(c + 1); LDB_ASYNC(c + 1, st ^ 1); }

        // compute on stage st
#pragma unroll
        for (int kk8 = 0; kk8 < 4; ++kk8) {
            float4 af[4];
#pragma unroll
            for (int i = 0; i < 4; ++i)
                af[i] = *(float4*)(sA[st] + ((kk8 * 8 + mo + i) * 32 + lane) * 4);
            float2 bf[8];
#pragma unroll
            for (int j = 0; j < 8; ++j)
                bf[j] = *(float2*)(sB[st] + ((kk8 * 256 + no + 8 * j + g) * 8 + t4 * 2));
#pragma unroll
            for (int i = 0; i < 4; ++i)
#pragma unroll
                for (int j = 0; j < 8; ++j)
                    mma_tf32(acc[i][j], af[i].x, af[i].y, af[i].z, af[i].w,
                             bf[j].x, bf[j].y);
        }

        if (more) STA(st ^ 1);
        cp_wait0();
        __syncthreads();
    }

    // ---- epilogue with bias
#pragma unroll
    for (int j = 0; j < 8; ++j) {
        int gn = no + 8 * j + 2 * t4;
        float2 bv = *(const float2*)(bias + gn);
#pragma unroll
        for (int i = 0; i < 4; ++i) {
            int gm = bm + (mo + i) * 16 + g;
            *(float2*)(C + (size_t)gm * 256 + gn) =
                make_float2(acc[i][j][0] + bv.x, acc[i][j][1] + bv.y);
            *(float2*)(C + (size_t)(gm + 8) * 256 + gn) =
                make_float2(acc[i][j][2] + bv.x, acc[i][j][3] + bv.y);
        }
    }
#undef LDA
#undef STA
#undef LDB_ASYNC
}

// ---------------------------------------------------------------------------
// Exact fp32 tiled GEMM with bias (small matrices)
// ---------------------------------------------------------------------------
__global__ __launch_bounds__(256, 2)
void gemm_bias_kernel(const float* __restrict__ A,
                      const float* __restrict__ W,
                      const float* __restrict__ bias,
                      float* __restrict__ C,
                      int M, int N, int K, int ldc)
{
    __shared__ float As[16][128];
    __shared__ float Bs[16][64];

    const int bm  = blockIdx.y * 128;
    const int bn  = blockIdx.x * 64;
    const int tid = threadIdx.x;
    const int tx  = tid & 15;
    const int ty  = tid >> 4;

    float acc[8][4];
#pragma unroll
    for (int i = 0; i < 8; ++i)
#pragma unroll
        for (int j = 0; j < 4; ++j) acc[i][j] = 0.f;

    const int a_row = tid >> 2;
    const int a_col = (tid & 3) << 2;
    const int b_row = tid >> 4;
    const int b_col = (tid & 15) << 2;

    for (int k0 = 0; k0 < K; k0 += 16) {
#pragma unroll
        for (int i = 0; i < 2; ++i) {
            int m  = a_row + i * 64;
            int gm = bm + m;
            float4 v = make_float4(0.f, 0.f, 0.f, 0.f);
            if (gm < M)
                v = *(const float4*)(A + (size_t)gm * K + k0 + a_col);
            As[a_col + 0][m] = v.x;
            As[a_col + 1][m] = v.y;
            As[a_col + 2][m] = v.z;
            As[a_col + 3][m] = v.w;
        }
        {
            int gn = bn + b_col;
            int gk = k0 + b_row;
            float4 v = make_float4(0.f, 0.f, 0.f, 0.f);
            if (gn + 3 < N) {
                v = *(const float4*)(W + (size_t)gk * N + gn);
            } else {
                float* pv = (float*)&v;
#pragma unroll
                for (int j = 0; j < 4; ++j)
                    if (gn + j < N) pv[j] = W[(size_t)gk * N + gn + j];
            }
            *(float4*)&Bs[b_row][b_col] = v;
        }
        __syncthreads();

#pragma unroll
        for (int k = 0; k < 16; ++k) {
            float4 a0 = *(const float4*)&As[k][ty * 8];
            float4 a1 = *(const float4*)&As[k][ty * 8 + 4];
            float4 b0 = *(const float4*)&Bs[k][tx * 4];
            float ra2[8] = {a0.x, a0.y, a0.z, a0.w, a1.x, a1.y, a1.z, a1.w};
            float rb[4] = {b0.x, b0.y, b0.z, b0.w};
#pragma unroll
            for (int i = 0; i < 8; ++i)
#pragma unroll
                for (int j = 0; j < 4; ++j)
                    acc[i][j] += ra2[i] * rb[j];
        }
        __syncthreads();
    }

    float bv[4];
#pragma unroll
    for (int j = 0; j < 4; ++j) {
        int gn = bn + tx * 4 + j;
        bv[j] = (gn < N) ? bias[gn] : 0.f;
    }
#pragma unroll
    for (int i = 0; i < 8; ++i) {
        int gm = bm + ty * 8 + i;
        if (gm >= M) continue;
#pragma unroll
        for (int j = 0; j < 4; ++j) {
            int gn = bn + tx * 4 + j;
            if (gn < N) C[(size_t)gm * ldc + gn] = acc[i][j] + bv[j];
        }
    }
}

// ---------------------------------------------------------------------------
// Deformable sampling + softmax. warp = head, lane = head-dim channel.
// ---------------------------------------------------------------------------
__global__ __launch_bounds__(256)
void sample_kernel(const float* __restrict__ ref,
                   float* __restrict__ out)
{
    const int row  = blockIdx.x;
    const int b    = row / LEN_Q;
    const int h    = threadIdx.x >> 5;
    const int lane = threadIdx.x & 31;

    const int   lvl_start[3] = {0, 6400, 8000};
    const int   lvl_W[3]     = {80, 40, 20};
    const float lvl_inv[3]   = {1.f / 80.f, 1.f / 40.f, 1.f / 20.f};

    const float* prm  = g_params + (size_t)row * P_LD;
    const float* offp = prm + h * (N_LP * 2);
    const float* attp = prm + 192 + h * N_LP;

    float lgt = (lane < N_LP) ? attp[lane] : -3.0e38f;
    float mx = lgt;
#pragma unroll
    for (int s = 16; s; s >>= 1) mx = fmaxf(mx, __shfl_xor_sync(0xffffffffu, mx, s));
    float e = (lane < N_LP) ? expf(lgt - mx) : 0.f;
    float sum = e;
#pragma unroll
    for (int s = 16; s; s >>= 1) sum += __shfl_xor_sync(0xffffffffu, sum, s);
    float wnorm = e / sum;

    const float* rp    = ref + (size_t)row * N_LEVELS * 2;
    const float* vbase = g_value + (size_t)b * N_TOTAL * D_MODEL + h * HEAD_DIM + lane;

    float acc = 0.f;
#pragma unroll
    for (int j = 0; j < N_LP; ++j) {
        const int l  = j >> 2;
        const int Wl = lvl_W[l];
        const int st = lvl_start[l];

        float aw = __shfl_sync(0xffffffffu, wnorm, j);

        float ox = offp[2 * j + 0];
        float oy = offp[2 * j + 1];
        float lx = rp[2 * l + 0] + ox * lvl_inv[l];
        float ly = rp[2 * l + 1] + oy * lvl_inv[l];

        float ix = lx * (float)Wl - 0.5f;
        float iy = ly * (float)Wl - 0.5f;
        float fix = floorf(ix), fiy = floorf(iy);
        int   x0 = (int)fix,   y0 = (int)fiy;
        float fx = ix - fix,   fy = iy - fiy;
        int   x1 = x0 + 1,     y1 = y0 + 1;

        bool vx0 = (x0 >= 0) & (x0 < Wl);
        bool vx1 = (x1 >= 0) & (x1 < Wl);
        bool vy0 = (y0 >= 0) & (y0 < Wl);
        bool vy1 = (y1 >= 0) & (y1 < Wl);

        float v00 = (vy0 & vx0) ? vbase[(size_t)(st + y0 * Wl + x0) * D_MODEL] : 0.f;
        float v01 = (vy0 & vx1) ? vbase[(size_t)(st + y0 * Wl + x1) * D_MODEL] : 0.f;
        float v10 = (vy1 & vx0) ? vbase[(size_t)(st + y1 * Wl + x0) * D_MODEL] : 0.f;
        float v11 = (vy1 & vx1) ? vbase[(size_t)(st + y1 * Wl + x1) * D_MODEL] : 0.f;

        float bil = (1.f - fx) * (1.f - fy) * v00 + fx * (1.f - fy) * v01
                  + (1.f - fx) * fy         * v10 + fx * fy         * v11;
        acc += aw * bil;
    }

    out[(size_t)row * D_MODEL + h * HEAD_DIM + lane] = acc;
}

// ---------------------------------------------------------------------------
extern "C" void kernel_launch(void* const* d_in, const int* in_sizes, int n_in,
                              void* d_out, int out_size)
{
    const float* query  = (const float*)d_in[0];
    const float* refpts = (const float*)d_in[1];
    const float* inputf = (const float*)d_in[2];
    const float* W_off  = (const float*)d_in[3];
    const float* b_off  = (const float*)d_in[4];
    const float* W_attn = (const float*)d_in[5];
    const float* b_attn = (const float*)d_in[6];
    const float* W_val  = (const float*)d_in[7];
    const float* b_val  = (const float*)d_in[8];
    const float* W_out  = (const float*)d_in[9];
    const float* b_out  = (const float*)d_in[10];
    float* outp = (float*)d_out;

    float* value;   cudaGetSymbolAddress((void**)&value,   g_value);
    float* params;  cudaGetSymbolAddress((void**)&params,  g_params);
    float* sampled; cudaGetSymbolAddress((void**)&sampled, g_sampled);

    cudaFuncSetAttribute(gemm1_mma_kernel,
                         cudaFuncAttributeMaxDynamicSharedMemorySize, GEMM1_DYN);

    // 0. W_val -> fragment-order tf32 buffer
    prep_w_kernel<<<256, 256>>>(W_val);

    // 1. value projection (mma.sync tf32): (134400,256)@(256,256)+b
    gemm1_mma_kernel<<<M1 / 128, 256, GEMM1_DYN>>>(inputf, b_val, value);

    // 2a. offsets (exact fp32)
    {
        dim3 grid((192 + 63) / 64, (NQ + 127) / 128);
        gemm_bias_kernel<<<grid, 256>>>(query, W_off, b_off, params,
                                        NQ, 192, D_MODEL, P_LD);
    }
    // 2b. attn logits (exact fp32)
    {
        dim3 grid((96 + 63) / 64, (NQ + 127) / 128);
        gemm_bias_kernel<<<grid, 256>>>(query, W_attn, b_attn, params + 192,
                                        NQ, 96, D_MODEL, P_LD);
    }
    // 3. softmax + deformable bilinear sampling
    sample_kernel<<<NQ, 256>>>(refpts, sampled);

    // 4. output projection (exact fp32)
    {
        dim3 grid(256 / 64, (NQ + 127) / 128);
        gemm_bias_kernel<<<grid, 256>>>(sampled, W_out, b_out, outp,
                                        NQ, D_MODEL, D_MODEL, D_MODEL);
    }
    (void)in_sizes; (void)n_in; (void)out_size;
}

// round 6
// speedup vs baseline: 2.7757x; 1.3567x over previous
#include <cuda_runtime.h>
#include <cuda_fp16.h>
#include <math.h>
#include <stdint.h>

#define D_MODEL   256
#define N_HEADS   8
#define HEAD_DIM  32
#define N_LEVELS  3
#define N_POINTS  4
#define N_LP      12
#define B_SZ      16
#define LEN_Q     300
#define N_TOTAL   8400
#define NQ        (B_SZ * LEN_Q)      // 4800
#define P_LD      288
#define M1        (B_SZ * N_TOTAL)    // 134400

// Scratch (__device__ globals per allocation-free rule)
__device__ float    g_value  [(size_t)M1 * D_MODEL];
__device__ float    g_params [(size_t)NQ * P_LD];
__device__ float    g_sampled[(size_t)NQ * D_MODEL];
__device__ uint32_t g_BfragH [32768];   // W_val as fp16x2 in B-fragment order

// ---------------------------------------------------------------------------
__device__ __forceinline__ uint32_t packh2(float lo, float hi) {
    __half2 h = __floats2half2_rn(lo, hi);
    return *(uint32_t*)&h;
}
__device__ __forceinline__ uint32_t smem_u32(const void* p) {
    uint32_t a;
    asm("{ .reg .u64 t; cvta.to.shared.u64 t, %1; cvt.u32.u64 %0, t; }"
        : "=r"(a) : "l"(p));
    return a;
}
__device__ __forceinline__ void cp_async16(uint32_t dst, const void* src) {
    asm volatile("cp.async.cg.shared.global [%0], [%1], 16;"
                 :: "r"(dst), "l"(src) : "memory");
}
__device__ __forceinline__ void cp_commit() {
    asm volatile("cp.async.commit_group;" ::: "memory");
}
__device__ __forceinline__ void cp_wait0() {
    asm volatile("cp.async.wait_group 0;" ::: "memory");
}
__device__ __forceinline__ void mma_f16(float c[4], uint32_t a0, uint32_t a1,
                                        uint32_t a2, uint32_t a3,
                                        uint32_t b0, uint32_t b1) {
    asm volatile(
        "mma.sync.aligned.m16n8k16.row.col.f32.f16.f16.f32 "
        "{%0,%1,%2,%3}, {%4,%5,%6,%7}, {%8,%9}, {%0,%1,%2,%3};"
        : "+f"(c[0]), "+f"(c[1]), "+f"(c[2]), "+f"(c[3])
        : "r"(a0), "r"(a1), "r"(a2), "r"(a3), "r"(b0), "r"(b1));
}

// ---------------------------------------------------------------------------
// W_val[k][n] -> fp16x2 B-fragment order.
// chunk kc (K=32), within chunk: idx = ((kk16*256+n)*4 + t4)*2 + half
//   word = fp16x2( W[k0][n], W[k0+1][n] ),  k0 = 32kc + 16kk16 + 8half + 2t4
// ---------------------------------------------------------------------------
__global__ void prep_w_kernel(const float* __restrict__ W) {
    int id = blockIdx.x * 256 + threadIdx.x;   // 0..32767
    int kc = id >> 12, ci = id & 4095;
    int half = ci & 1, t4v = (ci >> 1) & 3, n = (ci >> 3) & 255, kk16 = ci >> 11;
    int k0 = kc * 32 + kk16 * 16 + half * 8 + t4v * 2;
    g_BfragH[id] = packh2(W[(size_t)k0 * 256 + n], W[(size_t)(k0 + 1) * 256 + n]);
}

// ---------------------------------------------------------------------------
// GEMM1: C[M1,256] = A[M1,256] @ W_val + bias   (mma.sync fp16, fp32 accum)
// CTA 128x256, BK=32, double-buffered. 8 warps, warp tile 64x64.
// smem (uint32): sA 2x2048 (fragment order), sB 2x4096 (raw g_BfragH chunk)
// ---------------------------------------------------------------------------
#define GEMM1_DYN (48 * 1024)

__global__ __launch_bounds__(256, 1)
void gemm1_mma_kernel(const float* __restrict__ A,
                      const float* __restrict__ bias,
                      float* __restrict__ C)
{
    extern __shared__ uint32_t smw[];
    uint32_t* sA[2] = { smw,        smw + 2048 };
    uint32_t* sB[2] = { smw + 4096, smw + 8192 };

    const int tid  = threadIdx.x;
    const int warp = tid >> 5;
    const int lane = tid & 31;
    const int g    = lane >> 2;
    const int t4   = lane & 3;
    const int mo   = (warp >> 2) * 4;    // m16-tile base: 0 or 4
    const int no   = (warp & 3) * 64;    // n base
    const int bm   = blockIdx.x * 128;

    float acc[4][8][4];
#pragma unroll
    for (int i = 0; i < 4; ++i)
#pragma unroll
        for (int j = 0; j < 8; ++j)
#pragma unroll
            for (int r = 0; r < 4; ++r) acc[i][j][r] = 0.f;

    float4 ra[4];

#define LDA(c)                                                                 \
    do {                                                                       \
        _Pragma("unroll")                                                      \
        for (int i = 0; i < 4; ++i) {                                          \
            int idx = tid + i * 256;                                           \
            int ar = idx >> 3, ac = idx & 7;                                   \
            ra[i] = *(const float4*)(A + (size_t)(bm + ar) * 256 + (c) * 32 + ac * 4); \
        }                                                                      \
    } while (0)

#define STA(s)                                                                 \
    do {                                                                       \
        _Pragma("unroll")                                                      \
        for (int i = 0; i < 4; ++i) {                                          \
            int idx = tid + i * 256;                                           \
            int ar = idx >> 3, ac = idx & 7;                                   \
            int mt = ar >> 4, r = ar & 15;                                     \
            int gl = r & 7, hi = r >> 3;                                       \
            int kk16 = ac >> 2;                                                \
            int half = (ac & 3) >> 1;                                          \
            int t4v0 = (ac & 1) * 2;                                           \
            int base = ((kk16 * 8 + mt) * 32 + gl * 4 + t4v0) * 4 + half * 2 + hi; \
            sA[s][base]     = packh2(ra[i].x, ra[i].y);                        \
            sA[s][base + 4] = packh2(ra[i].z, ra[i].w);                        \
        }                                                                      \
    } while (0)

#define LDB_ASYNC(c, s)                                                        \
    do {                                                                       \
        uint32_t base = smem_u32(sB[s]);                                       \
        const uint32_t* src = g_BfragH + (size_t)(c) * 4096;                   \
        _Pragma("unroll")                                                      \
        for (int i = 0; i < 4; ++i) {                                          \
            int off = (tid + i * 256) * 4;                                     \
            cp_async16(base + off * 4, src + off);                             \
        }                                                                      \
        cp_commit();                                                           \
    } while (0)

    LDA(0);
    LDB_ASYNC(0, 0);
    STA(0);
    cp_wait0();
    __syncthreads();

#pragma unroll 1
    for (int c = 0; c < 8; ++c) {
        const int st = c & 1;
        const bool more = (c < 7);
        if (more) { LDA(c + 1); LDB_ASYNC(c + 1, st ^ 1); }

#pragma unroll
        for (int kk16 = 0; kk16 < 2; ++kk16) {
            uint4 af[4];
#pragma unroll
            for (int i = 0; i < 4; ++i)
                af[i] = *(uint4*)&sA[st][((kk16 * 8 + mo + i) * 32 + lane) * 4];
            uint2 bf[8];
#pragma unroll
            for (int j = 0; j < 8; ++j)
                bf[j] = *(uint2*)&sB[st][((kk16 * 256 + no + 8 * j + g) * 4 + t4) * 2];
#pragma unroll
            for (int i = 0; i < 4; ++i)
#pragma unroll
                for (int j = 0; j < 8; ++j)
                    mma_f16(acc[i][j], af[i].x, af[i].y, af[i].z, af[i].w,
                            bf[j].x, bf[j].y);
        }

        if (more) STA(st ^ 1);
        cp_wait0();
        __syncthreads();
    }

    // epilogue with bias
#pragma unroll
    for (int j = 0; j < 8; ++j) {
        int gn = no + 8 * j + 2 * t4;
        float2 bv = *(const float2*)(bias + gn);
#pragma unroll
        for (int i = 0; i < 4; ++i) {
            int gm = bm + (mo + i) * 16 + g;
            *(float2*)(C + (size_t)gm * 256 + gn) =
                make_float2(acc[i][j][0] + bv.x, acc[i][j][1] + bv.y);
            *(float2*)(C + (size_t)(gm + 8) * 256 + gn) =
                make_float2(acc[i][j][2] + bv.x, acc[i][j][3] + bv.y);
        }
    }
#undef LDA
#undef STA
#undef LDB_ASYNC
}

// ---------------------------------------------------------------------------
// Small-GEMM kernel (exact fp32), 64x64 tiles, per-thread 4x4, 256 threads.
// Supports column-concatenated weights: cols [0,N1) from W1/b1 (row stride
// N1), cols [N1,N) from W2/b2 (row stride N2 = N-N1). Requires M%64==0,
// K%16==0.
// ---------------------------------------------------------------------------
__global__ __launch_bounds__(256, 4)
void gemm64_kernel(const float* __restrict__ A,
                   const float* __restrict__ W1, const float* __restrict__ b1,
                   const float* __restrict__ W2, const float* __restrict__ b2,
                   int N1, int N2,
                   float* __restrict__ C,
                   int N, int K, int ldc)
{
    __shared__ float As[16][68];
    __shared__ float Bs[16][68];

    const int bm  = blockIdx.y * 64;
    const int bn  = blockIdx.x * 64;
    const int tid = threadIdx.x;
    const int tx  = tid & 15;
    const int ty  = tid >> 4;

    float acc[4][4];
#pragma unroll
    for (int i = 0; i < 4; ++i)
#pragma unroll
        for (int j = 0; j < 4; ++j) acc[i][j] = 0.f;

    const int a_row = tid >> 2;          // 0..63
    const int a_col = (tid & 3) << 2;    // 0,4,8,12
    const int b_row = tid >> 4;          // 0..15
    const int b_col = (tid & 15) << 2;   // 0..60

    for (int k0 = 0; k0 < K; k0 += 16) {
        {
            float4 v = *(const float4*)(A + (size_t)(bm + a_row) * K + k0 + a_col);
            As[a_col + 0][a_row] = v.x;
            As[a_col + 1][a_row] = v.y;
            As[a_col + 2][a_row] = v.z;
            As[a_col + 3][a_row] = v.w;
        }
        {
            int gk = k0 + b_row;
            float v[4];
#pragma unroll
            for (int e = 0; e < 4; ++e) {
                int gn = bn + b_col + e;
                float x = 0.f;
                if (gn < N1)       x = W1[(size_t)gk * N1 + gn];
                else if (gn < N)   x = W2[(size_t)gk * N2 + gn - N1];
                v[e] = x;
            }
            *(float4*)&Bs[b_row][b_col] = make_float4(v[0], v[1], v[2], v[3]);
        }
        __syncthreads();

#pragma unroll
        for (int k = 0; k < 16; ++k) {
            float4 a4 = *(const float4*)&As[k][ty * 4];
            float4 b4 = *(const float4*)&Bs[k][tx * 4];
            float ar2[4] = {a4.x, a4.y, a4.z, a4.w};
            float br2[4] = {b4.x, b4.y, b4.z, b4.w};
#pragma unroll
            for (int i = 0; i < 4; ++i)
#pragma unroll
                for (int j = 0; j < 4; ++j)
                    acc[i][j] += ar2[i] * br2[j];
        }
        __syncthreads();
    }

    float bv[4];
#pragma unroll
    for (int j = 0; j < 4; ++j) {
        int gn = bn + tx * 4 + j;
        bv[j] = (gn < N1) ? b1[gn] : ((gn < N) ? b2[gn - N1] : 0.f);
    }
#pragma unroll
    for (int i = 0; i < 4; ++i) {
        int gm = bm + ty * 4 + i;
#pragma unroll
        for (int j = 0; j < 4; ++j) {
            int gn = bn + tx * 4 + j;
            if (gn < N) C[(size_t)gm * ldc + gn] = acc[i][j] + bv[j];
        }
    }
}

// ---------------------------------------------------------------------------
// Deformable sampling + softmax. warp = head, lane = head-dim channel.
// ---------------------------------------------------------------------------
__global__ __launch_bounds__(256)
void sample_kernel(const float* __restrict__ ref,
                   float* __restrict__ out)
{
    const int row  = blockIdx.x;
    const int b    = row / LEN_Q;
    const int h    = threadIdx.x >> 5;
    const int lane = threadIdx.x & 31;

    const int   lvl_start[3] = {0, 6400, 8000};
    const int   lvl_W[3]     = {80, 40, 20};
    const float lvl_inv[3]   = {1.f / 80.f, 1.f / 40.f, 1.f / 20.f};

    const float* prm  = g_params + (size_t)row * P_LD;
    const float* offp = prm + h * (N_LP * 2);
    const float* attp = prm + 192 + h * N_LP;

    float lgt = (lane < N_LP) ? attp[lane] : -3.0e38f;
    float mx = lgt;
#pragma unroll
    for (int s = 16; s; s >>= 1) mx = fmaxf(mx, __shfl_xor_sync(0xffffffffu, mx, s));
    float e = (lane < N_LP) ? expf(lgt - mx) : 0.f;
    float sum = e;
#pragma unroll
    for (int s = 16; s; s >>= 1) sum += __shfl_xor_sync(0xffffffffu, sum, s);
    float wnorm = e / sum;

    const float* rp    = ref + (size_t)row * N_LEVELS * 2;
    const float* vbase = g_value + (size_t)b * N_TOTAL * D_MODEL + h * HEAD_DIM + lane;

    float acc = 0.f;
#pragma unroll
    for (int j = 0; j < N_LP; ++j) {
        const int l  = j >> 2;
        const int Wl = lvl_W[l];
        const int st = lvl_start[l];

        float aw = __shfl_sync(0xffffffffu, wnorm, j);

        float ox = offp[2 * j + 0];
        float oy = offp[2 * j + 1];
        float lx = rp[2 * l + 0] + ox * lvl_inv[l];
        float ly = rp[2 * l + 1] + oy * lvl_inv[l];

        float ix = lx * (float)Wl - 0.5f;
        float iy = ly * (float)Wl - 0.5f;
        float fix = floorf(ix), fiy = floorf(iy);
        int   x0 = (int)fix,   y0 = (int)fiy;
        float fx = ix - fix,   fy = iy - fiy;
        int   x1 = x0 + 1,     y1 = y0 + 1;

        bool vx0 = (x0 >= 0) & (x0 < Wl);
        bool vx1 = (x1 >= 0) & (x1 < Wl);
        bool vy0 = (y0 >= 0) & (y0 < Wl);
        bool vy1 = (y1 >= 0) & (y1 < Wl);

        float v00 = (vy0 & vx0) ? vbase[(size_t)(st + y0 * Wl + x0) * D_MODEL] : 0.f;
        float v01 = (vy0 & vx1) ? vbase[(size_t)(st + y0 * Wl + x1) * D_MODEL] : 0.f;
        float v10 = (vy1 & vx0) ? vbase[(size_t)(st + y1 * Wl + x0) * D_MODEL] : 0.f;
        float v11 = (vy1 & vx1) ? vbase[(size_t)(st + y1 * Wl + x1) * D_MODEL] : 0.f;

        float bil = (1.f - fx) * (1.f - fy) * v00 + fx * (1.f - fy) * v01
                  + (1.f - fx) * fy         * v10 + fx * fy         * v11;
        acc += aw * bil;
    }

    out[(size_t)row * D_MODEL + h * HEAD_DIM + lane] = acc;
}

// ---------------------------------------------------------------------------
extern "C" void kernel_launch(void* const* d_in, const int* in_sizes, int n_in,
                              void* d_out, int out_size)
{
    const float* query  = (const float*)d_in[0];
    const float* refpts = (const float*)d_in[1];
    const float* inputf = (const float*)d_in[2];
    const float* W_off  = (const float*)d_in[3];
    const float* b_off  = (const float*)d_in[4];
    const float* W_attn = (const float*)d_in[5];
    const float* b_attn = (const float*)d_in[6];
    const float* W_val  = (const float*)d_in[7];
    const float* b_val  = (const float*)d_in[8];
    const float* W_out  = (const float*)d_in[9];
    const float* b_out  = (const float*)d_in[10];
    float* outp = (float*)d_out;

    float* value;   cudaGetSymbolAddress((void**)&value,   g_value);
    float* params;  cudaGetSymbolAddress((void**)&params,  g_params);
    float* sampled; cudaGetSymbolAddress((void**)&sampled, g_sampled);

    cudaFuncSetAttribute(gemm1_mma_kernel,
                         cudaFuncAttributeMaxDynamicSharedMemorySize, GEMM1_DYN);

    // 0. W_val -> fp16 fragment-order buffer
    prep_w_kernel<<<128, 256>>>(W_val);

    // 1. value projection (mma.sync fp16): (134400,256)@(256,256)+b
    gemm1_mma_kernel<<<M1 / 128, 256, GEMM1_DYN>>>(inputf, b_val, value);

    // 2. fused offsets+attn: (4800,256)@(256,288)+b -> params
    {
        dim3 grid((P_LD + 63) / 64, NQ / 64);   // 5 x 75
        gemm64_kernel<<<grid, 256>>>(query, W_off, b_off, W_attn, b_attn,
                                     192, 96, params, P_LD, D_MODEL, P_LD);
    }
    // 3. softmax + deformable bilinear sampling
    sample_kernel<<<NQ, 256>>>(refpts, sampled);

    // 4. output projection: (4800,256)@(256,256)+b -> d_out
    {
        dim3 grid(256 / 64, NQ / 64);           // 4 x 75
        gemm64_kernel<<<grid, 256>>>(sampled, W_out, b_out, W_out, b_out,
                                     256, 256, outp, 256, D_MODEL, 256);
    }
    (void)in_sizes; (void)n_in; (void)out_size;
}